// round 4
// baseline (speedup 1.0000x reference)
#include <cuda_runtime.h>
#include <math.h>
#include <stdint.h>

// Problem constants
#define BB   8
#define DD   64      // FIN
#define NN   2048
#define KK   20      // k neighbors
#define CC   128     // 2*FIN edge-feature channels
#define O1   256     // conv1 out channels
#define J1   10      // conv1 output spatial (20-11+1)
#define T1   11      // conv1 kernel width
#define O2C  256     // conv2 out channels
#define SS   40      // conv2 kernel width (full window)
#define GN   4       // points per knn block
#define G1   4       // points per conv1 block
#define G2   8       // points per conv2 block

// ---------------- scratch (static device globals; no allocs) ----------------
__device__ float g_sq[BB * NN];
__device__ int   g_idx[BB * NN * KK];
__device__ float g_ee[(size_t)BB * NN * CC * KK];   // [b][n][c][k]  ~168MB
__device__ float g_h [(size_t)BB * NN * O1 * J1];   // [b][n][o][j]  ~168MB
__device__ float g_bn1a[O1];
__device__ float g_bn1b[O1];
__device__ float g_y [BB * NN * O2C];               // [b][n][o2]    ~16.8MB
__device__ float g_bn2a[O2C];
__device__ float g_bn2b[O2C];

// ---------------- kernel 1: squared norms ----------------
// Reference materializes xt*xt (rounded fp32 multiply) then sums sequentially
// over the last axis. Match that exactly: NO fma contraction here.
__global__ void k_sq(const float* __restrict__ x) {
    int i = blockIdx.x * 256 + threadIdx.x;      // B*N = 16384
    if (i >= BB * NN) return;
    int b = i / NN, n = i % NN;
    const float* xb = x + (size_t)b * DD * NN + n;
    float s = 0.f;
#pragma unroll
    for (int d = 0; d < DD; d++) {
        float v = xb[(size_t)d * NN];
        s = __fadd_rn(s, __fmul_rn(v, v));   // fl(v*v) then fl(add) — like the ref
    }
    g_sq[i] = s;
}

// ---------------- kernel 2: kNN (top-20 ascending distance, tie->lower idx) ----
// dot: sequential FFMA over d (matches GEMM-backend K-loop accumulation).
// dist: fl(fl(sq_n + sq_m) - fl(2*dot)) in exactly that association.
__global__ void __launch_bounds__(256) k_knn(const float* __restrict__ x) {
    int b  = blockIdx.x / (NN / GN);
    int n0 = (blockIdx.x % (NN / GN)) * GN;
    __shared__ float xn[GN][DD];
    __shared__ float dist[GN][NN];      // 32KB
    __shared__ float rv[256];
    __shared__ int   ri[256];
    __shared__ int   winner;
    int tid = threadIdx.x;

    const float* xb = x + (size_t)b * DD * NN;
    for (int i = tid; i < GN * DD; i += 256) {
        int g = i / DD, d = i % DD;
        xn[g][d] = xb[(size_t)d * NN + n0 + g];
    }
    __syncthreads();

    float sqn[GN];
#pragma unroll
    for (int g = 0; g < GN; g++) sqn[g] = g_sq[b * NN + n0 + g];

    // 8 m-values per thread (2048/256)
    float dot[GN][8];
#pragma unroll
    for (int g = 0; g < GN; g++)
#pragma unroll
        for (int i = 0; i < 8; i++) dot[g][i] = 0.f;

    for (int d = 0; d < DD; d++) {
        float xv[8];
#pragma unroll
        for (int i = 0; i < 8; i++) xv[i] = xb[(size_t)d * NN + tid + 256 * i];
#pragma unroll
        for (int g = 0; g < GN; g++) {
            float xnv = xn[g][d];
#pragma unroll
            for (int i = 0; i < 8; i++) dot[g][i] = __fmaf_rn(xnv, xv[i], dot[g][i]);
        }
    }
#pragma unroll
    for (int i = 0; i < 8; i++) {
        int m = tid + 256 * i;
        float sm = g_sq[b * NN + m];
#pragma unroll
        for (int g = 0; g < GN; g++) {
            float t  = __fadd_rn(sqn[g], sm);             // fl(sq_n + sq_m)
            float u  = __fmul_rn(2.f, dot[g][i]);         // exact (power of 2)
            float dv = __fsub_rn(t, u);                   // fl(t - 2*dot)
            dist[g][m] = (m == n0 + g) ? 1e30f : dv;      // exclude self (always rank 0)
        }
    }
    __syncthreads();

    for (int g = 0; g < GN; g++) {
        for (int kk = 0; kk < KK; kk++) {
            float bv = 1e30f; int bi = NN;
            for (int m = tid; m < NN; m += 256) {
                float v = dist[g][m];
                if (v < bv) { bv = v; bi = m; }   // strided m increasing -> lowest idx on tie
            }
            rv[tid] = bv; ri[tid] = bi;
            __syncthreads();
            for (int s = 128; s > 0; s >>= 1) {
                if (tid < s) {
                    float v2 = rv[tid + s]; int i2 = ri[tid + s];
                    if (v2 < rv[tid] || (v2 == rv[tid] && i2 < ri[tid])) {
                        rv[tid] = v2; ri[tid] = i2;
                    }
                }
                __syncthreads();
            }
            if (tid == 0) {
                winner = ri[0];
                g_idx[(b * NN + n0 + g) * KK + kk] = ri[0];
            }
            __syncthreads();
            if (tid == 0) dist[g][winner] = 1e30f;
            __syncthreads();
        }
    }
}

// ---------------- kernel 3: build edge features + conv1 (fused) ----------------
__global__ void __launch_bounds__(256) k_conv1(const float* __restrict__ x,
                                               const float* __restrict__ w1,
                                               const float* __restrict__ b1) {
    int b  = blockIdx.x / (NN / G1);
    int n0 = (blockIdx.x % (NN / G1)) * G1;
    __shared__ float ee_s[G1][CC][KK];   // 40KB
    int tid = threadIdx.x;
    const float* xb = x + (size_t)b * DD * NN;

    for (int i = tid; i < G1 * CC * KK; i += 256) {
        int g = i / (CC * KK);
        int r = i % (CC * KK);
        int c = r / KK;
        int k = r % KK;
        int n = n0 + g;
        float v;
        if (c < DD) {
            v = xb[(size_t)c * NN + n];                       // central (k-broadcast)
        } else {
            int m = g_idx[(b * NN + n) * KK + k];
            int d = c - DD;
            v = xb[(size_t)d * NN + m] - xb[(size_t)d * NN + n];  // neighbor - central
        }
        ee_s[g][c][k] = v;
        g_ee[(((size_t)(b * NN + n)) * CC + c) * KK + k] = v;
    }
    __syncthreads();

    int o = tid;   // one output channel per thread
    float acc[G1][J1];
#pragma unroll
    for (int g = 0; g < G1; g++)
#pragma unroll
        for (int j = 0; j < J1; j++) acc[g][j] = 0.f;

    for (int c = 0; c < CC; c++) {
        float w[T1];
#pragma unroll
        for (int t = 0; t < T1; t++) w[t] = w1[(o * CC + c) * T1 + t];
#pragma unroll
        for (int g = 0; g < G1; g++) {
            float e[KK];
#pragma unroll
            for (int s = 0; s < KK; s++) e[s] = ee_s[g][c][s];   // broadcast LDS
#pragma unroll
            for (int j = 0; j < J1; j++)
#pragma unroll
                for (int t = 0; t < T1; t++)
                    acc[g][j] += e[j + t] * w[t];
        }
    }
    float bias = b1[o];
#pragma unroll
    for (int g = 0; g < G1; g++)
#pragma unroll
        for (int j = 0; j < J1; j++)
            g_h[(((size_t)(b * NN + n0 + g)) * O1 + o) * J1 + j] = acc[g][j] + bias;
}

// ---------------- kernel 4: BN1 stats (deterministic tree reduction) ------------
__global__ void k_bn1(const float* __restrict__ gamma, const float* __restrict__ beta) {
    int o = blockIdx.x;
    int tid = threadIdx.x;
    float s = 0.f, s2 = 0.f;
    for (int p = tid; p < BB * NN; p += 256) {
        const float* hp = &g_h[((size_t)p * O1 + o) * J1];
#pragma unroll
        for (int j = 0; j < J1; j++) { float v = hp[j]; s += v; s2 += v * v; }
    }
    __shared__ float rs[256], rs2[256];
    rs[tid] = s; rs2[tid] = s2;
    __syncthreads();
    for (int t = 128; t > 0; t >>= 1) {
        if (tid < t) { rs[tid] += rs[tid + t]; rs2[tid] += rs2[tid + t]; }
        __syncthreads();
    }
    if (tid == 0) {
        float cnt  = (float)(BB * NN * J1);
        float mean = rs[0] / cnt;
        float var  = rs2[0] / cnt - mean * mean;
        float a    = gamma[o] * rsqrtf(var + 1e-5f);
        g_bn1a[o] = a;
        g_bn1b[o] = beta[o] - mean * a;
    }
}

// ---------------- kernel 5: conv2 over merged features ----------------
// merge[...,0:20] = ee ; merge[...,20:40] = inte where inte[c][k] maps to
// bn1+leaky(h) at (o = 2c + (k>=10), j = k%10)  -> contiguous 20 floats in hp_s.
__global__ void __launch_bounds__(256) k_conv2(const float* __restrict__ w2,
                                               const float* __restrict__ b2) {
    extern __shared__ float smem[];
    float* ee_s = smem;                      // G2*CC*KK = 20480 floats
    float* hp_s = smem + G2 * CC * KK;       // G2*O1*J1 = 20480 floats
    int b  = blockIdx.x / (NN / G2);
    int n0 = (blockIdx.x % (NN / G2)) * G2;
    int tid = threadIdx.x;

    size_t base = ((size_t)(b * NN + n0)) * CC * KK;
    for (int i = tid; i < G2 * CC * KK; i += 256) ee_s[i] = g_ee[base + i];

    size_t baseh = ((size_t)(b * NN + n0)) * O1 * J1;
    for (int i = tid; i < G2 * O1 * J1; i += 256) {
        float raw = g_h[baseh + i];
        int o = (i % (O1 * J1)) / J1;
        float v = g_bn1a[o] * raw + g_bn1b[o];
        hp_s[i] = v > 0.f ? v : 0.01f * v;   // leaky relu
    }
    __syncthreads();

    int o2 = tid;
    float acc[G2];
#pragma unroll
    for (int g = 0; g < G2; g++) acc[g] = 0.f;

    for (int c = 0; c < CC; c++) {
        float w[SS];
#pragma unroll
        for (int s = 0; s < SS; s++) w[s] = w2[(o2 * CC + c) * SS + s];
#pragma unroll
        for (int g = 0; g < G2; g++) {
            const float* eg = &ee_s[(g * CC + c) * KK];
            const float* hg = &hp_s[(g * O1 + 2 * c) * J1];   // rows 2c and 2c+1 contiguous
            float a = acc[g];
#pragma unroll
            for (int k = 0; k < KK; k++) a += eg[k] * w[k];
#pragma unroll
            for (int k = 0; k < 2 * J1; k++) a += hg[k] * w[KK + k];
            acc[g] = a;
        }
    }
    float bias = b2[o2];
#pragma unroll
    for (int g = 0; g < G2; g++)
        g_y[(b * NN + n0 + g) * O2C + o2] = acc[g] + bias;
}

// ---------------- kernel 6: BN2 stats ----------------
__global__ void k_bn2(const float* __restrict__ gamma, const float* __restrict__ beta) {
    int o = blockIdx.x;
    int tid = threadIdx.x;
    float s = 0.f, s2 = 0.f;
    for (int p = tid; p < BB * NN; p += 256) {
        float v = g_y[(size_t)p * O2C + o];
        s += v; s2 += v * v;
    }
    __shared__ float rs[256], rs2[256];
    rs[tid] = s; rs2[tid] = s2;
    __syncthreads();
    for (int t = 128; t > 0; t >>= 1) {
        if (tid < t) { rs[tid] += rs[tid + t]; rs2[tid] += rs2[tid + t]; }
        __syncthreads();
    }
    if (tid == 0) {
        float cnt  = (float)(BB * NN);
        float mean = rs[0] / cnt;
        float var  = rs2[0] / cnt - mean * mean;
        float a    = gamma[o] * rsqrtf(var + 1e-5f);
        g_bn2a[o] = a;
        g_bn2b[o] = beta[o] - mean * a;
    }
}

// ---------------- kernel 7: BN2 apply + relu + reshape to (B,128,4096) ----------
__global__ void k_out(float* __restrict__ out) {
    int i = blockIdx.x * 256 + threadIdx.x;   // 8*128*4096 = 4194304
    if (i >= BB * 128 * 4096) return;
    int b = i >> 19;             // /(128*4096)
    int r = i & 524287;
    int f = r >> 12;             // /4096
    int m = r & 4095;
    int o2 = f * 2 + (m >> 11);  // y.reshape(B,128,4096): lin = o2*2048+n
    int n  = m & 2047;
    float v = g_bn2a[o2] * g_y[(b * NN + n) * O2C + o2] + g_bn2b[o2];
    out[i] = v > 0.f ? v : 0.f;
}

// ---------------- launch ----------------
extern "C" void kernel_launch(void* const* d_in, const int* in_sizes, int n_in,
                              void* d_out, int out_size) {
    const float* x   = (const float*)d_in[0];
    const float* w1  = (const float*)d_in[1];
    const float* b1  = (const float*)d_in[2];
    const float* g1  = (const float*)d_in[3];
    const float* be1 = (const float*)d_in[4];
    const float* w2  = (const float*)d_in[5];
    const float* b2  = (const float*)d_in[6];
    const float* g2  = (const float*)d_in[7];
    const float* be2 = (const float*)d_in[8];
    float* out = (float*)d_out;

    k_sq  <<<(BB * NN + 255) / 256, 256>>>(x);
    k_knn <<<BB * NN / GN, 256>>>(x);
    k_conv1<<<BB * NN / G1, 256>>>(x, w1, b1);
    k_bn1 <<<O1, 256>>>(g1, be1);

    int smem2 = (G2 * CC * KK + G2 * O1 * J1) * (int)sizeof(float);  // 160KB
    cudaFuncSetAttribute(k_conv2, cudaFuncAttributeMaxDynamicSharedMemorySize, smem2);
    k_conv2<<<BB * NN / G2, 256, smem2>>>(w2, b2);

    k_bn2 <<<O2C, 256>>>(g2, be2);
    k_out <<<(BB * 128 * 4096) / 256, 256>>>(out);
}

// round 5
// speedup vs baseline: 2.8217x; 2.8217x over previous
#include <cuda_runtime.h>
#include <math.h>
#include <stdint.h>

// Problem constants
#define BB   8
#define DD   64      // FIN
#define NN   2048
#define KK   20      // k neighbors
#define CC   128     // 2*FIN edge-feature channels
#define O1   256     // conv1 out channels
#define J1   10      // conv1 output spatial (20-11+1)
#define T1   11      // conv1 kernel width
#define O2C  256     // conv2 out channels
#define SS   40      // conv2 kernel width (full window)
#define GN   4       // points per knn block
#define G1   4       // points per conv1 block
#define G2P  32      // points per conv2 chunk block
#define CCH  32      // conv2 c-chunk size
#define NCH  4       // conv2 chunk passes
#define RPAD 34      // conv2 smem row stride (g-dim padded: even + low-conflict)

typedef unsigned long long ull;

__device__ __forceinline__ ull fma2(ull a, ull b, ull c) {
    ull d;
    asm("fma.rn.f32x2 %0, %1, %2, %3;" : "=l"(d) : "l"(a), "l"(b), "l"(c));
    return d;
}
__device__ __forceinline__ ull dup2(float v) {
    ull d; unsigned int u = __float_as_uint(v);
    asm("mov.b64 %0, {%1, %1};" : "=l"(d) : "r"(u));
    return d;
}
__device__ __forceinline__ float2 unpk(ull v) {
    float2 r;
    asm("mov.b64 {%0, %1}, %2;" : "=f"(r.x), "=f"(r.y) : "l"(v));
    return r;
}

// ---------------- scratch (static device globals; no allocs) ----------------
__device__ float g_sq[BB * NN];
__device__ int   g_idx[BB * NN * KK];
__device__ float g_ee[(size_t)BB * NN * CC * KK];   // [b][n][m=c*20+k]
__device__ float g_h [(size_t)BB * NN * O1 * J1];   // [b][n][o][j]
__device__ float g_bn1a[O1];
__device__ float g_bn1b[O1];
__device__ float g_y [BB * NN * O2C];               // [b][n][o2]
__device__ float g_bn2a[O2C];
__device__ float g_bn2b[O2C];
__device__ float g_w1t[CC * O1 * T1];               // [c][o][t]
__device__ float g_w2t[CC * SS * O2C];              // [c][s][o2]

// ---------------- weight transposes (one-time per launch, trivial) ----------
__global__ void k_tw1(const float* __restrict__ w1) {
    int i = blockIdx.x * 256 + threadIdx.x;
    if (i >= CC * O1 * T1) return;
    int o = i / (CC * T1);
    int r = i % (CC * T1);
    int c = r / T1, t = r % T1;
    g_w1t[(c * O1 + o) * T1 + t] = w1[i];
}
__global__ void k_tw2(const float* __restrict__ w2) {
    int i = blockIdx.x * 256 + threadIdx.x;
    if (i >= CC * SS * O2C) return;
    int o = i / (CC * SS);
    int r = i % (CC * SS);
    int c = r / SS, s = r % SS;
    g_w2t[(c * SS + s) * O2C + o] = w2[i];
}

// ---------------- kernel 1: squared norms (mul-then-add, matches ref) --------
__global__ void k_sq(const float* __restrict__ x) {
    int i = blockIdx.x * 256 + threadIdx.x;      // B*N = 16384
    if (i >= BB * NN) return;
    int b = i / NN, n = i % NN;
    const float* xb = x + (size_t)b * DD * NN + n;
    float s = 0.f;
#pragma unroll
    for (int d = 0; d < DD; d++) {
        float v = xb[(size_t)d * NN];
        s = __fadd_rn(s, __fmul_rn(v, v));
    }
    g_sq[i] = s;
}

// ---------------- kernel 2: kNN (exact association as R3 — do not touch) ----
__global__ void __launch_bounds__(256) k_knn(const float* __restrict__ x) {
    int b  = blockIdx.x / (NN / GN);
    int n0 = (blockIdx.x % (NN / GN)) * GN;
    __shared__ float xn[GN][DD];
    __shared__ float dist[GN][NN];
    __shared__ float rv[256];
    __shared__ int   ri[256];
    __shared__ int   winner;
    int tid = threadIdx.x;

    const float* xb = x + (size_t)b * DD * NN;
    for (int i = tid; i < GN * DD; i += 256) {
        int g = i / DD, d = i % DD;
        xn[g][d] = xb[(size_t)d * NN + n0 + g];
    }
    __syncthreads();

    float sqn[GN];
#pragma unroll
    for (int g = 0; g < GN; g++) sqn[g] = g_sq[b * NN + n0 + g];

    float dot[GN][8];
#pragma unroll
    for (int g = 0; g < GN; g++)
#pragma unroll
        for (int i = 0; i < 8; i++) dot[g][i] = 0.f;

    for (int d = 0; d < DD; d++) {
        float xv[8];
#pragma unroll
        for (int i = 0; i < 8; i++) xv[i] = xb[(size_t)d * NN + tid + 256 * i];
#pragma unroll
        for (int g = 0; g < GN; g++) {
            float xnv = xn[g][d];
#pragma unroll
            for (int i = 0; i < 8; i++) dot[g][i] = __fmaf_rn(xnv, xv[i], dot[g][i]);
        }
    }
#pragma unroll
    for (int i = 0; i < 8; i++) {
        int m = tid + 256 * i;
        float sm = g_sq[b * NN + m];
#pragma unroll
        for (int g = 0; g < GN; g++) {
            float t  = __fadd_rn(sqn[g], sm);
            float u  = __fmul_rn(2.f, dot[g][i]);
            float dv = __fsub_rn(t, u);
            dist[g][m] = (m == n0 + g) ? 1e30f : dv;
        }
    }
    __syncthreads();

    for (int g = 0; g < GN; g++) {
        for (int kk = 0; kk < KK; kk++) {
            float bv = 1e30f; int bi = NN;
            for (int m = tid; m < NN; m += 256) {
                float v = dist[g][m];
                if (v < bv) { bv = v; bi = m; }
            }
            rv[tid] = bv; ri[tid] = bi;
            __syncthreads();
            for (int s = 128; s > 0; s >>= 1) {
                if (tid < s) {
                    float v2 = rv[tid + s]; int i2 = ri[tid + s];
                    if (v2 < rv[tid] || (v2 == rv[tid] && i2 < ri[tid])) {
                        rv[tid] = v2; ri[tid] = i2;
                    }
                }
                __syncthreads();
            }
            if (tid == 0) {
                winner = ri[0];
                g_idx[(b * NN + n0 + g) * KK + kk] = ri[0];
            }
            __syncthreads();
            if (tid == 0) dist[g][winner] = 1e30f;
            __syncthreads();
        }
    }
}

// ---------------- kernel 3: edge features + conv1 (FFMA2 + smem weights) ----
// dyn smem: ee_s[2560][G1] (40KB) + w_s[2][O1*T1] (22.5KB) = 63.5KB
__global__ void __launch_bounds__(256) k_conv1(const float* __restrict__ x,
                                               const float* __restrict__ b1) {
    extern __shared__ float smem[];
    float* ee_s = smem;                   // [m = c*20+k][g], stride G1
    float* w_s  = smem + CC * KK * G1;    // [2][O1*T1]
    int b  = blockIdx.x / (NN / G1);
    int n0 = (blockIdx.x % (NN / G1)) * G1;
    int tid = threadIdx.x;
    const float* xb = x + (size_t)b * DD * NN;

    for (int i = tid; i < G1 * CC * KK; i += 256) {
        int g = i / (CC * KK);
        int m = i % (CC * KK);
        int c = m / KK, k = m % KK;
        int n = n0 + g;
        float v;
        if (c < DD) {
            v = xb[(size_t)c * NN + n];
        } else {
            int mm = g_idx[(b * NN + n) * KK + k];
            int d = c - DD;
            v = xb[(size_t)d * NN + mm] - xb[(size_t)d * NN + n];
        }
        ee_s[m * G1 + g] = v;
        g_ee[(size_t)(b * NN + n) * (CC * KK) + m] = v;
    }
    // preload weights for c=0
    for (int i = tid; i < O1 * T1; i += 256) w_s[i] = g_w1t[i];
    __syncthreads();

    int o = tid;
    ull acc[2][J1];
#pragma unroll
    for (int p = 0; p < 2; p++)
#pragma unroll
        for (int j = 0; j < J1; j++) acc[p][j] = 0ull;

    for (int c = 0; c < CC; c++) {
        int cur = c & 1;
        if (c + 1 < CC) {
            const float* src = &g_w1t[(c + 1) * (O1 * T1)];
            float* dst = &w_s[(cur ^ 1) * (O1 * T1)];
            for (int i = tid; i < O1 * T1; i += 256) dst[i] = src[i];
        }
        ull wd[T1];
#pragma unroll
        for (int t = 0; t < T1; t++) wd[t] = dup2(w_s[cur * (O1 * T1) + o * T1 + t]);
        const float* ers = &ee_s[c * KK * G1];
#pragma unroll
        for (int p = 0; p < 2; p++) {
            ull e[KK];
#pragma unroll
            for (int k = 0; k < KK; k++)
                e[k] = *(const ull*)&ers[k * G1 + 2 * p];
#pragma unroll
            for (int j = 0; j < J1; j++)
#pragma unroll
                for (int t = 0; t < T1; t++)
                    acc[p][j] = fma2(e[j + t], wd[t], acc[p][j]);
        }
        __syncthreads();
    }
    float bias = b1[o];
#pragma unroll
    for (int p = 0; p < 2; p++)
#pragma unroll
        for (int j = 0; j < J1; j++) {
            float2 v = unpk(acc[p][j]);
            g_h[((size_t)(b * NN + n0 + 2 * p)     * O1 + o) * J1 + j] = v.x + bias;
            g_h[((size_t)(b * NN + n0 + 2 * p + 1) * O1 + o) * J1 + j] = v.y + bias;
        }
}

// ---------------- kernel 4: BN1 stats ----------------
__global__ void k_bn1(const float* __restrict__ gamma, const float* __restrict__ beta) {
    int o = blockIdx.x;
    int tid = threadIdx.x;
    float s = 0.f, s2 = 0.f;
    for (int p = tid; p < BB * NN; p += 256) {
        const float* hp = &g_h[((size_t)p * O1 + o) * J1];
#pragma unroll
        for (int j = 0; j < J1; j++) { float v = hp[j]; s += v; s2 += v * v; }
    }
    __shared__ float rs[256], rs2[256];
    rs[tid] = s; rs2[tid] = s2;
    __syncthreads();
    for (int t = 128; t > 0; t >>= 1) {
        if (tid < t) { rs[tid] += rs[tid + t]; rs2[tid] += rs2[tid + t]; }
        __syncthreads();
    }
    if (tid == 0) {
        float cnt  = (float)(BB * NN * J1);
        float mean = rs[0] / cnt;
        float var  = rs2[0] / cnt - mean * mean;
        float a    = gamma[o] * rsqrtf(var + 1e-5f);
        g_bn1a[o] = a;
        g_bn1b[o] = beta[o] - mean * a;
    }
}

// ---------------- kernel 5: conv2, c-chunked (FFMA2, coalesced weights) -------
// Grid per pass: (BB*NN/G2P) blocks; chunk c0 = pass*CCH.
// dyn smem: ee2[CCH*20][RPAD] + hp2[CCH*20][RPAD] = 2*640*34 floats = 174KB
__global__ void __launch_bounds__(256) k_conv2c(const float* __restrict__ b2, int pass) {
    extern __shared__ float smem[];
    float* ee2 = smem;                    // [cl*20+k][g] stride RPAD
    float* hp2 = smem + CCH * KK * RPAD;
    int b  = blockIdx.x / (NN / G2P);
    int n0 = (blockIdx.x % (NN / G2P)) * G2P;
    int c0 = pass * CCH;
    int tid = threadIdx.x;

    // stage ee chunk: m in [0, CCH*20)
    for (int i = tid; i < G2P * CCH * KK; i += 256) {
        int g = i / (CCH * KK);
        int m = i % (CCH * KK);
        ee2[m * RPAD + g] = g_ee[(size_t)(b * NN + n0 + g) * (CC * KK) + c0 * KK + m];
    }
    // stage hp chunk with BN1 + leaky: linear index within point = c*20+s = c0*20+m
    for (int i = tid; i < G2P * CCH * KK; i += 256) {
        int g = i / (CCH * KK);
        int m = i % (CCH * KK);
        int lin = c0 * KK + m;            // = o*10 + j
        int o = lin / J1;
        float raw = g_h[(size_t)(b * NN + n0 + g) * (O1 * J1) + lin];
        float v = g_bn1a[o] * raw + g_bn1b[o];
        hp2[m * RPAD + g] = v > 0.f ? v : 0.01f * v;
    }
    __syncthreads();

    int o2 = tid;
    ull acc[G2P / 2];
#pragma unroll
    for (int p = 0; p < G2P / 2; p++) acc[p] = 0ull;

    for (int cl = 0; cl < CCH; cl++) {
        const float* wrow = &g_w2t[((c0 + cl) * SS) * O2C + o2];
        const float* er = &ee2[cl * KK * RPAD];
        const float* hr = &hp2[cl * KK * RPAD];
#pragma unroll 4
        for (int s = 0; s < KK; s++) {
            ull wd = dup2(wrow[s * O2C]);
            const float* row = &er[s * RPAD];
#pragma unroll
            for (int p = 0; p < G2P / 2; p++)
                acc[p] = fma2(*(const ull*)&row[2 * p], wd, acc[p]);
        }
#pragma unroll 4
        for (int s = 0; s < KK; s++) {
            ull wd = dup2(wrow[(KK + s) * O2C]);
            const float* row = &hr[s * RPAD];
#pragma unroll
            for (int p = 0; p < G2P / 2; p++)
                acc[p] = fma2(*(const ull*)&row[2 * p], wd, acc[p]);
        }
    }

    if (pass == 0) {
        float bias = b2[o2];
#pragma unroll
        for (int p = 0; p < G2P / 2; p++) {
            float2 v = unpk(acc[p]);
            g_y[(b * NN + n0 + 2 * p)     * O2C + o2] = v.x + bias;
            g_y[(b * NN + n0 + 2 * p + 1) * O2C + o2] = v.y + bias;
        }
    } else {
#pragma unroll
        for (int p = 0; p < G2P / 2; p++) {
            float2 v = unpk(acc[p]);
            g_y[(b * NN + n0 + 2 * p)     * O2C + o2] += v.x;
            g_y[(b * NN + n0 + 2 * p + 1) * O2C + o2] += v.y;
        }
    }
}

// ---------------- kernel 6: BN2 stats ----------------
__global__ void k_bn2(const float* __restrict__ gamma, const float* __restrict__ beta) {
    int o = blockIdx.x;
    int tid = threadIdx.x;
    float s = 0.f, s2 = 0.f;
    for (int p = tid; p < BB * NN; p += 256) {
        float v = g_y[(size_t)p * O2C + o];
        s += v; s2 += v * v;
    }
    __shared__ float rs[256], rs2[256];
    rs[tid] = s; rs2[tid] = s2;
    __syncthreads();
    for (int t = 128; t > 0; t >>= 1) {
        if (tid < t) { rs[tid] += rs[tid + t]; rs2[tid] += rs2[tid + t]; }
        __syncthreads();
    }
    if (tid == 0) {
        float cnt  = (float)(BB * NN);
        float mean = rs[0] / cnt;
        float var  = rs2[0] / cnt - mean * mean;
        float a    = gamma[o] * rsqrtf(var + 1e-5f);
        g_bn2a[o] = a;
        g_bn2b[o] = beta[o] - mean * a;
    }
}

// ---------------- kernel 7: BN2 apply + relu + reshape ----------------
__global__ void k_out(float* __restrict__ out) {
    int i = blockIdx.x * 256 + threadIdx.x;   // 8*128*4096
    if (i >= BB * 128 * 4096) return;
    int b = i >> 19;
    int r = i & 524287;
    int f = r >> 12;
    int m = r & 4095;
    int o2 = f * 2 + (m >> 11);
    int n  = m & 2047;
    float v = g_bn2a[o2] * g_y[(b * NN + n) * O2C + o2] + g_bn2b[o2];
    out[i] = v > 0.f ? v : 0.f;
}

// ---------------- launch ----------------
extern "C" void kernel_launch(void* const* d_in, const int* in_sizes, int n_in,
                              void* d_out, int out_size) {
    const float* x   = (const float*)d_in[0];
    const float* w1  = (const float*)d_in[1];
    const float* b1  = (const float*)d_in[2];
    const float* g1  = (const float*)d_in[3];
    const float* be1 = (const float*)d_in[4];
    const float* w2  = (const float*)d_in[5];
    const float* b2  = (const float*)d_in[6];
    const float* g2  = (const float*)d_in[7];
    const float* be2 = (const float*)d_in[8];
    float* out = (float*)d_out;

    static int attr_done = 0;
    int smem1 = (CC * KK * G1 + 2 * O1 * T1) * (int)sizeof(float);       // 63.5KB
    int smem2 = (2 * CCH * KK * RPAD) * (int)sizeof(float);              // 174KB
    if (!attr_done) {
        cudaFuncSetAttribute(k_conv1,  cudaFuncAttributeMaxDynamicSharedMemorySize, smem1);
        cudaFuncSetAttribute(k_conv2c, cudaFuncAttributeMaxDynamicSharedMemorySize, smem2);
        attr_done = 1;
    }

    k_tw1 <<<(CC * O1 * T1 + 255) / 256, 256>>>(w1);
    k_tw2 <<<(CC * SS * O2C + 255) / 256, 256>>>(w2);
    k_sq  <<<(BB * NN + 255) / 256, 256>>>(x);
    k_knn <<<BB * NN / GN, 256>>>(x);
    k_conv1<<<BB * NN / G1, 256, smem1>>>(x, b1);
    k_bn1 <<<O1, 256>>>(g1, be1);
    for (int p = 0; p < NCH; p++)
        k_conv2c<<<BB * NN / G2P, 256, smem2>>>(b2, p);
    k_bn2 <<<O2C, 256>>>(g2, be2);
    k_out <<<(BB * 128 * 4096) / 256, 256>>>(out);
}